// round 1
// baseline (speedup 1.0000x reference)
#include <cuda_runtime.h>
#include <math.h>

#define Bdim 4096
#define DIN  512
#define Hdim 512
#define Edim 256
#define Vdim 512
#define Ldim 32
#define MIN_REAL (-3.4028234663852886e38f)

// ---------------- scratch (device globals; no allocation allowed) ----------
__device__ float g_h[2][(size_t)Bdim * Hdim];   // ping-pong hidden state
__device__ float g_e[(size_t)Bdim * Edim];      // current embedding input
__device__ float g_logits[(size_t)Bdim * Vdim]; // per-step logits

// ---------------- e0 = broadcast sos ---------------------------------------
__global__ void init_e0_kernel(const float* __restrict__ sos) {
    int i = blockIdx.x * blockDim.x + threadIdx.x;
    g_e[i] = sos[i & (Edim - 1)];
}

// ---------------- generic C[M,N] = A[M,K](lda) @ W[N,K]^T + bias ------------
// 64x64 tile, K-tile 16, 256 threads, 4x4 micro-tile per thread.
__global__ __launch_bounds__(256) void gemm_bias_kernel(
    const float* __restrict__ A, int lda,
    const float* __restrict__ W, int K,
    const float* __restrict__ bias,
    float* __restrict__ C, int ldc)
{
    __shared__ float As[16][64];
    __shared__ float Ws[16][64];
    const int tid = threadIdx.x;
    const int m0 = blockIdx.y * 64, n0 = blockIdx.x * 64;
    const int lr = tid >> 2;            // 0..63 row within tile for loading
    const int lq = (tid & 3) * 4;       // k-quad for loading
    const int tx = tid & 15, ty = tid >> 4;
    const int row0 = ty * 4, col0 = tx * 4;

    float acc[4][4];
#pragma unroll
    for (int i = 0; i < 4; i++)
#pragma unroll
        for (int j = 0; j < 4; j++) acc[i][j] = 0.f;

    for (int k0 = 0; k0 < K; k0 += 16) {
        float4 av = *(const float4*)&A[(size_t)(m0 + lr) * lda + k0 + lq];
        float4 wv = *(const float4*)&W[(size_t)(n0 + lr) * K   + k0 + lq];
        __syncthreads();
        As[lq + 0][lr] = av.x; As[lq + 1][lr] = av.y;
        As[lq + 2][lr] = av.z; As[lq + 3][lr] = av.w;
        Ws[lq + 0][lr] = wv.x; Ws[lq + 1][lr] = wv.y;
        Ws[lq + 2][lr] = wv.z; Ws[lq + 3][lr] = wv.w;
        __syncthreads();
#pragma unroll
        for (int k = 0; k < 16; k++) {
            float4 a = *(const float4*)&As[k][row0];
            float4 w = *(const float4*)&Ws[k][col0];
            float aa[4] = {a.x, a.y, a.z, a.w};
            float ww[4] = {w.x, w.y, w.z, w.w};
#pragma unroll
            for (int i = 0; i < 4; i++)
#pragma unroll
                for (int j = 0; j < 4; j++) acc[i][j] = fmaf(aa[i], ww[j], acc[i][j]);
        }
    }
#pragma unroll
    for (int i = 0; i < 4; i++) {
        float* crow = &C[(size_t)(m0 + row0 + i) * ldc + n0 + col0];
#pragma unroll
        for (int j = 0; j < 4; j++) crow[j] = acc[i][j] + bias[n0 + col0 + j];
    }
}

// ---------------- fused GRU gates + state update ----------------------------
// For output column tile j0..j0+63 of h_new:
//   aR,aZ accumulate e@W_ih + h@W_hh rows (g, g+H)
//   aN1 accumulates e@W_ih rows (2H+j)   (input part of n)
//   aN2 accumulates h@W_hh rows (2H+j)   (hidden part of n; gets scaled by r)
__global__ __launch_bounds__(256) void gru_gates_kernel(
    const float* __restrict__ e,     // [B, E]
    const float* __restrict__ hin,   // [B, H]
    const float* __restrict__ W_ih,  // [3H, E]
    const float* __restrict__ W_hh,  // [3H, H]
    const float* __restrict__ b_ih,  // [3H]
    const float* __restrict__ b_hh,  // [3H]
    float* __restrict__ hout)        // [B, H]
{
    __shared__ float As[16][64];
    __shared__ float Wr[16][64];
    __shared__ float Wz[16][64];
    __shared__ float Wn[16][64];
    const int tid = threadIdx.x;
    const int m0 = blockIdx.y * 64, j0 = blockIdx.x * 64;
    const int lr = tid >> 2;
    const int lq = (tid & 3) * 4;
    const int tx = tid & 15, ty = tid >> 4;
    const int row0 = ty * 4, col0 = tx * 4;

    float aR[4][4], aZ[4][4], aN1[4][4], aN2[4][4];
#pragma unroll
    for (int i = 0; i < 4; i++)
#pragma unroll
        for (int j = 0; j < 4; j++) { aR[i][j]=0.f; aZ[i][j]=0.f; aN1[i][j]=0.f; aN2[i][j]=0.f; }

    // ---- phase 1: input (e) contributions, K = E ----
    for (int k0 = 0; k0 < Edim; k0 += 16) {
        float4 av = *(const float4*)&e[(size_t)(m0 + lr) * Edim + k0 + lq];
        float4 r4 = *(const float4*)&W_ih[(size_t)(0 * Hdim + j0 + lr) * Edim + k0 + lq];
        float4 z4 = *(const float4*)&W_ih[(size_t)(1 * Hdim + j0 + lr) * Edim + k0 + lq];
        float4 n4 = *(const float4*)&W_ih[(size_t)(2 * Hdim + j0 + lr) * Edim + k0 + lq];
        __syncthreads();
        As[lq+0][lr]=av.x; As[lq+1][lr]=av.y; As[lq+2][lr]=av.z; As[lq+3][lr]=av.w;
        Wr[lq+0][lr]=r4.x; Wr[lq+1][lr]=r4.y; Wr[lq+2][lr]=r4.z; Wr[lq+3][lr]=r4.w;
        Wz[lq+0][lr]=z4.x; Wz[lq+1][lr]=z4.y; Wz[lq+2][lr]=z4.z; Wz[lq+3][lr]=z4.w;
        Wn[lq+0][lr]=n4.x; Wn[lq+1][lr]=n4.y; Wn[lq+2][lr]=n4.z; Wn[lq+3][lr]=n4.w;
        __syncthreads();
#pragma unroll
        for (int k = 0; k < 16; k++) {
            float4 a = *(const float4*)&As[k][row0];
            float4 wr = *(const float4*)&Wr[k][col0];
            float4 wz = *(const float4*)&Wz[k][col0];
            float4 wn = *(const float4*)&Wn[k][col0];
            float aa[4] = {a.x,a.y,a.z,a.w};
            float rr[4] = {wr.x,wr.y,wr.z,wr.w};
            float zz[4] = {wz.x,wz.y,wz.z,wz.w};
            float nn[4] = {wn.x,wn.y,wn.z,wn.w};
#pragma unroll
            for (int i = 0; i < 4; i++)
#pragma unroll
                for (int j = 0; j < 4; j++) {
                    aR [i][j] = fmaf(aa[i], rr[j], aR [i][j]);
                    aZ [i][j] = fmaf(aa[i], zz[j], aZ [i][j]);
                    aN1[i][j] = fmaf(aa[i], nn[j], aN1[i][j]);
                }
        }
    }
    // ---- phase 2: hidden (h) contributions, K = H ----
    for (int k0 = 0; k0 < Hdim; k0 += 16) {
        float4 av = *(const float4*)&hin[(size_t)(m0 + lr) * Hdim + k0 + lq];
        float4 r4 = *(const float4*)&W_hh[(size_t)(0 * Hdim + j0 + lr) * Hdim + k0 + lq];
        float4 z4 = *(const float4*)&W_hh[(size_t)(1 * Hdim + j0 + lr) * Hdim + k0 + lq];
        float4 n4 = *(const float4*)&W_hh[(size_t)(2 * Hdim + j0 + lr) * Hdim + k0 + lq];
        __syncthreads();
        As[lq+0][lr]=av.x; As[lq+1][lr]=av.y; As[lq+2][lr]=av.z; As[lq+3][lr]=av.w;
        Wr[lq+0][lr]=r4.x; Wr[lq+1][lr]=r4.y; Wr[lq+2][lr]=r4.z; Wr[lq+3][lr]=r4.w;
        Wz[lq+0][lr]=z4.x; Wz[lq+1][lr]=z4.y; Wz[lq+2][lr]=z4.z; Wz[lq+3][lr]=z4.w;
        Wn[lq+0][lr]=n4.x; Wn[lq+1][lr]=n4.y; Wn[lq+2][lr]=n4.z; Wn[lq+3][lr]=n4.w;
        __syncthreads();
#pragma unroll
        for (int k = 0; k < 16; k++) {
            float4 a = *(const float4*)&As[k][row0];
            float4 wr = *(const float4*)&Wr[k][col0];
            float4 wz = *(const float4*)&Wz[k][col0];
            float4 wn = *(const float4*)&Wn[k][col0];
            float aa[4] = {a.x,a.y,a.z,a.w};
            float rr[4] = {wr.x,wr.y,wr.z,wr.w};
            float zz[4] = {wz.x,wz.y,wz.z,wz.w};
            float nn[4] = {wn.x,wn.y,wn.z,wn.w};
#pragma unroll
            for (int i = 0; i < 4; i++)
#pragma unroll
                for (int j = 0; j < 4; j++) {
                    aR [i][j] = fmaf(aa[i], rr[j], aR [i][j]);
                    aZ [i][j] = fmaf(aa[i], zz[j], aZ [i][j]);
                    aN2[i][j] = fmaf(aa[i], nn[j], aN2[i][j]);
                }
        }
    }

    // ---- epilogue: gates + state update ----
#pragma unroll
    for (int j = 0; j < 4; j++) {
        int jg = j0 + col0 + j;
        float br = b_ih[jg]            + b_hh[jg];
        float bz = b_ih[Hdim + jg]     + b_hh[Hdim + jg];
        float bni = b_ih[2 * Hdim + jg];
        float bnh = b_hh[2 * Hdim + jg];
#pragma unroll
        for (int i = 0; i < 4; i++) {
            int bg = m0 + row0 + i;
            float r = 1.f / (1.f + expf(-(aR[i][j] + br)));
            float z = 1.f / (1.f + expf(-(aZ[i][j] + bz)));
            float n = tanhf(aN1[i][j] + bni + r * (aN2[i][j] + bnh));
            float hold = hin[(size_t)bg * Hdim + jg];
            hout[(size_t)bg * Hdim + jg] = (1.f - z) * n + z * hold;
        }
    }
}

// ---------------- gumbel softmax + entropy + write outputs ------------------
// One warp per row; V=512 -> 16 elems/lane.
__global__ __launch_bounds__(256) void softmax_kernel(
    const float* __restrict__ logits,
    const float* __restrict__ u,       // noise slab for this step [B, V]
    float* __restrict__ seq,           // d_out sequence base [B, L, V]
    float* __restrict__ ent,           // d_out entropy base [B, L]
    int l)
{
    const int warp = threadIdx.x >> 5, lane = threadIdx.x & 31;
    const int b = blockIdx.x * 8 + warp;
    const float* lrow = logits + (size_t)b * Vdim;
    const float* urow = u + (size_t)b * Vdim;

    float s[16];
    float m = -INFINITY;
#pragma unroll
    for (int i = 0; i < 16; i++) {
        float uu = urow[lane + 32 * i];
        float g = -logf(-logf(uu));
        s[i] = lrow[lane + 32 * i] + g;
        m = fmaxf(m, s[i]);
    }
#pragma unroll
    for (int o = 16; o; o >>= 1) m = fmaxf(m, __shfl_xor_sync(0xffffffffu, m, o));

    float sum = 0.f;
#pragma unroll
    for (int i = 0; i < 16; i++) { s[i] = expf(s[i] - m); sum += s[i]; }
#pragma unroll
    for (int o = 16; o; o >>= 1) sum += __shfl_xor_sync(0xffffffffu, sum, o);

    float inv = 1.f / sum;
    float eacc = 0.f;
    float* srow = seq + ((size_t)b * Ldim + l) * Vdim;
#pragma unroll
    for (int i = 0; i < 16; i++) {
        float p = s[i] * inv;
        srow[lane + 32 * i] = p;
        float t = fmaxf(log2f(p), MIN_REAL);   // log2(0) = -inf -> clamped
        eacc -= p * t;                         // p==0 -> contribution 0
    }
#pragma unroll
    for (int o = 16; o; o >>= 1) eacc += __shfl_xor_sync(0xffffffffu, eacc, o);
    if (lane == 0) ent[(size_t)b * Ldim + l] = eacc;
}

// ---------------- host launcher ---------------------------------------------
extern "C" void kernel_launch(void* const* d_in, const int* in_sizes, int n_in,
                              void* d_out, int out_size)
{
    const float* x       = (const float*)d_in[0];
    const float* noise   = (const float*)d_in[1];
    const float* W_agent = (const float*)d_in[2];
    const float* b_agent = (const float*)d_in[3];
    const float* W_ih    = (const float*)d_in[4];
    const float* W_hh    = (const float*)d_in[5];
    const float* b_ih    = (const float*)d_in[6];
    const float* b_hh    = (const float*)d_in[7];
    const float* W_out   = (const float*)d_in[8];
    const float* b_out   = (const float*)d_in[9];
    const float* W_emb   = (const float*)d_in[10];
    const float* b_emb   = (const float*)d_in[11];
    const float* sos     = (const float*)d_in[12];

    float* out = (float*)d_out;                         // sequence [B, L, V]
    float* ent = out + (size_t)Bdim * Ldim * Vdim;      // entropies [B, L]

    // resolve scratch addresses (host-side lookup; no stream work, capture-safe)
    float *hbuf0, *hbuf1, *ebuf, *lbuf;
    cudaGetSymbolAddress((void**)&hbuf0, g_h);
    hbuf1 = hbuf0 + (size_t)Bdim * Hdim;
    cudaGetSymbolAddress((void**)&ebuf, g_e);
    cudaGetSymbolAddress((void**)&lbuf, g_logits);

    // e0 = broadcast(sos)
    init_e0_kernel<<<(Bdim * Edim) / 256, 256>>>(sos);

    // h0 = x @ W_agent^T + b_agent
    gemm_bias_kernel<<<dim3(Hdim / 64, Bdim / 64), 256>>>(
        x, DIN, W_agent, DIN, b_agent, hbuf0, Hdim);

    for (int l = 0; l < Ldim; l++) {
        float* hin  = (l & 1) ? hbuf1 : hbuf0;
        float* hout = (l & 1) ? hbuf0 : hbuf1;

        // h_t  (fused gates GEMM + GRU update)
        gru_gates_kernel<<<dim3(Hdim / 64, Bdim / 64), 256>>>(
            ebuf, hin, W_ih, W_hh, b_ih, b_hh, hout);

        // logits = h_t @ W_out^T + b_out
        gemm_bias_kernel<<<dim3(Vdim / 64, Bdim / 64), 256>>>(
            hout, Hdim, W_out, Hdim, b_out, lbuf, Vdim);

        // sample = softmax(logits + gumbel); entropy; write outputs
        softmax_kernel<<<Bdim / 8, 256>>>(
            lbuf, noise + (size_t)l * Bdim * Vdim, out, ent, l);

        // e_{l+1} = sample @ W_emb^T + b_emb  (sample read back from d_out)
        gemm_bias_kernel<<<dim3(Edim / 64, Bdim / 64), 256>>>(
            out + (size_t)l * Vdim, Ldim * Vdim, W_emb, Vdim, b_emb, ebuf, Edim);
    }
    (void)in_sizes; (void)n_in; (void)out_size;
}

// round 3
// speedup vs baseline: 1.7476x; 1.7476x over previous
#include <cuda_runtime.h>
#include <math.h>
#include <stdint.h>

#define Bdim 4096
#define DIN  512
#define Hdim 512
#define Edim 256
#define Vdim 512
#define Ldim 32
#define MIN_REAL (-3.4028234663852886e38f)

// ---------------- scratch (device globals; no allocation allowed) ----------
__device__ float g_h[2][(size_t)Bdim * Hdim];     // ping-pong hidden state
__device__ float g_e[(size_t)Bdim * Edim];        // current embedding input
__device__ float g_logits[(size_t)Bdim * Vdim];   // per-step logits
__device__ float g_gi[(size_t)Bdim * 3 * Hdim];   // e @ W_ih^T + b_ih
__device__ float g_gh[(size_t)Bdim * 3 * Hdim];   // h @ W_hh^T + b_hh

__device__ __forceinline__ uint32_t tf32b(float x) {
    uint32_t o;
    asm("cvt.rn.tf32.f32 %0, %1;" : "=r"(o) : "f"(x));
    return o;
}
__device__ __forceinline__ float sigm(float x) { return 1.f / (1.f + expf(-x)); }

#define MMA_TF32(d, av, bv) \
    asm volatile("mma.sync.aligned.m16n8k8.row.col.f32.tf32.tf32.f32 " \
        "{%0,%1,%2,%3}, {%4,%5,%6,%7}, {%8,%9}, {%0,%1,%2,%3};" \
        : "+f"((d)[0]), "+f"((d)[1]), "+f"((d)[2]), "+f"((d)[3]) \
        : "r"((av).x), "r"((av).y), "r"((av).z), "r"((av).w), \
          "r"((bv).x), "r"((bv).y))

// ---------------- e0 = broadcast sos ---------------------------------------
__global__ void init_e0_kernel(const float* __restrict__ sos) {
    int i = blockIdx.x * blockDim.x + threadIdx.x;
    g_e[i] = sos[i & (Edim - 1)];
}

// ======================= tf32 tensor-core GEMM ==============================
// C[M,N] = A[M,K] @ W[N,K]^T + bias.  Block tile 128(M) x 64(N), K-block 32.
// 128 threads = 4 warps; each warp: 32(M) x 64(N) = 2 m-frags x 8 n-frags of
// m16n8k8.  SMEM tiles stored in fragment-permuted order (conflict-free LDS).
__global__ __launch_bounds__(128) void gemm_tc(
    const float* __restrict__ A, int lda,
    const float* __restrict__ W, int K,
    const float* __restrict__ bias,
    float* __restrict__ C, int ldc)
{
    extern __shared__ uint32_t sm[];      // A: [2][4096], B: [2][2048] @ 8192
    const int tid = threadIdx.x, wid = tid >> 5, lane = tid & 31;
    const int m0 = blockIdx.y << 7, n0 = blockIdx.x << 6;
    const int KB = K >> 5;

    float acc[2][8][4];
#pragma unroll
    for (int a = 0; a < 2; a++)
#pragma unroll
        for (int b = 0; b < 8; b++)
#pragma unroll
            for (int c = 0; c < 4; c++) acc[a][b][c] = 0.f;

    float4 ra[8], rb[4];

    auto load_regs = [&](int kb) {
#pragma unroll
        for (int it = 0; it < 8; ++it) {
            int i = tid + (it << 7), r = i >> 3, q = i & 7;
            ra[it] = __ldg((const float4*)&A[(size_t)(m0 + r) * lda + (kb << 5) + (q << 2)]);
        }
#pragma unroll
        for (int it = 0; it < 4; ++it) {
            int i = tid + (it << 7), n = i >> 3, q = i & 7;
            rb[it] = __ldg((const float4*)&W[(size_t)(n0 + n) * K + (kb << 5) + (q << 2)]);
        }
    };
    auto store_smem = [&](int s) {
#pragma unroll
        for (int it = 0; it < 8; ++it) {
            int i = tid + (it << 7), r = i >> 3, q = i & 7;
            int mtile = r >> 4, rr = r & 15, tg = rr & 7, half = rr >> 3;
            int kt = q >> 1, v = half + ((q & 1) << 1);
            uint32_t* p = &sm[(s << 12) + (((kt << 3) + mtile) << 7) + (tg << 4) + v];
            p[0]  = tf32b(ra[it].x);
            p[4]  = tf32b(ra[it].y);
            p[8]  = tf32b(ra[it].z);
            p[12] = tf32b(ra[it].w);
        }
#pragma unroll
        for (int it = 0; it < 4; ++it) {
            int i = tid + (it << 7), n = i >> 3, q = i & 7;
            int ntile = n >> 3, nn = n & 7, kt = q >> 1, v = q & 1;
            uint32_t* p = &sm[8192 + (s << 11) + (((kt << 3) + ntile) << 6) + (nn << 3) + v];
            p[0] = tf32b(rb[it].x);
            p[2] = tf32b(rb[it].y);
            p[4] = tf32b(rb[it].z);
            p[6] = tf32b(rb[it].w);
        }
    };
    auto compute = [&](int s) {
#pragma unroll
        for (int kt = 0; kt < 4; ++kt) {
            uint4 a0 = *(const uint4*)&sm[(s << 12) + (((kt << 3) + (wid << 1) + 0) << 7) + (lane << 2)];
            uint4 a1 = *(const uint4*)&sm[(s << 12) + (((kt << 3) + (wid << 1) + 1) << 7) + (lane << 2)];
            uint2 bf[8];
#pragma unroll
            for (int nt = 0; nt < 8; ++nt)
                bf[nt] = *(const uint2*)&sm[8192 + (s << 11) + (((kt << 3) + nt) << 6) + (lane << 1)];
#pragma unroll
            for (int nt = 0; nt < 8; ++nt) {
                MMA_TF32(acc[0][nt], a0, bf[nt]);
                MMA_TF32(acc[1][nt], a1, bf[nt]);
            }
        }
    };

    load_regs(0);
    store_smem(0);
    __syncthreads();
    for (int kb = 0; kb < KB; ++kb) {
        if (kb + 1 < KB) load_regs(kb + 1);
        compute(kb & 1);
        if (kb + 1 < KB) {
            __syncthreads();
            store_smem((kb + 1) & 1);
            __syncthreads();
        }
    }

    // epilogue: bias + store (float2)
#pragma unroll
    for (int mt = 0; mt < 2; ++mt) {
#pragma unroll
        for (int nt = 0; nt < 8; ++nt) {
            int row = m0 + (wid << 5) + (mt << 4) + (lane >> 2);
            int col = n0 + (nt << 3) + ((lane & 3) << 1);
            float2 bv = *(const float2*)&bias[col];
            float2 o0 = {acc[mt][nt][0] + bv.x, acc[mt][nt][1] + bv.y};
            float2 o1 = {acc[mt][nt][2] + bv.x, acc[mt][nt][3] + bv.y};
            *(float2*)&C[(size_t)row * ldc + col] = o0;
            *(float2*)&C[(size_t)(row + 8) * ldc + col] = o1;
        }
    }
}

// ======================= elementwise GRU update =============================
// hout = (1-z)*n + z*h  with r,z,n from Gi/Gh slabs (biases already added).
__global__ __launch_bounds__(256) void gru_ew(
    const float4* __restrict__ Gi, const float4* __restrict__ Gh,
    const float4* __restrict__ hin, float4* __restrict__ hout)
{
    int i = blockIdx.x * blockDim.x + threadIdx.x;   // B*128 float4 rows
    int b = i >> 7, jq = i & 127;
    float4 ir = Gi[(size_t)b * 384 + jq];
    float4 iz = Gi[(size_t)b * 384 + 128 + jq];
    float4 in_ = Gi[(size_t)b * 384 + 256 + jq];
    float4 hr = Gh[(size_t)b * 384 + jq];
    float4 hz = Gh[(size_t)b * 384 + 128 + jq];
    float4 hn = Gh[(size_t)b * 384 + 256 + jq];
    float4 h = hin[(size_t)b * 128 + jq];
    float4 o;
    {
        float r = sigm(ir.x + hr.x), z = sigm(iz.x + hz.x);
        o.x = (1.f - z) * tanhf(in_.x + r * hn.x) + z * h.x;
    }
    {
        float r = sigm(ir.y + hr.y), z = sigm(iz.y + hz.y);
        o.y = (1.f - z) * tanhf(in_.y + r * hn.y) + z * h.y;
    }
    {
        float r = sigm(ir.z + hr.z), z = sigm(iz.z + hz.z);
        o.z = (1.f - z) * tanhf(in_.z + r * hn.z) + z * h.z;
    }
    {
        float r = sigm(ir.w + hr.w), z = sigm(iz.w + hz.w);
        o.w = (1.f - z) * tanhf(in_.w + r * hn.w) + z * h.w;
    }
    hout[(size_t)b * 128 + jq] = o;
}

// ======================= gumbel softmax + entropy ===========================
__global__ __launch_bounds__(256) void softmax_kernel(
    const float* __restrict__ logits, const float* __restrict__ u,
    float* __restrict__ seq, float* __restrict__ ent, int l)
{
    const int warp = threadIdx.x >> 5, lane = threadIdx.x & 31;
    const int b = blockIdx.x * 8 + warp;
    const float* lrow = logits + (size_t)b * Vdim;
    const float* urow = u + (size_t)b * Vdim;

    float s[16];
    float m = -INFINITY;
#pragma unroll
    for (int i = 0; i < 16; i++) {
        float uu = urow[lane + 32 * i];
        float g = -logf(-logf(uu));
        s[i] = lrow[lane + 32 * i] + g;
        m = fmaxf(m, s[i]);
    }
#pragma unroll
    for (int o = 16; o; o >>= 1) m = fmaxf(m, __shfl_xor_sync(0xffffffffu, m, o));
    float sum = 0.f;
#pragma unroll
    for (int i = 0; i < 16; i++) { s[i] = expf(s[i] - m); sum += s[i]; }
#pragma unroll
    for (int o = 16; o; o >>= 1) sum += __shfl_xor_sync(0xffffffffu, sum, o);

    float inv = 1.f / sum;
    float eacc = 0.f;
    float* srow = seq + ((size_t)b * Ldim + l) * Vdim;
#pragma unroll
    for (int i = 0; i < 16; i++) {
        float p = s[i] * inv;
        srow[lane + 32 * i] = p;
        float t = fmaxf(log2f(p), MIN_REAL);   // log2(0) = -inf -> clamped
        eacc -= p * t;                         // p==0 -> contribution 0
    }
#pragma unroll
    for (int o = 16; o; o >>= 1) eacc += __shfl_xor_sync(0xffffffffu, eacc, o);
    if (lane == 0) ent[(size_t)b * Ldim + l] = eacc;
}

// ======================= host launcher ======================================
extern "C" void kernel_launch(void* const* d_in, const int* in_sizes, int n_in,
                              void* d_out, int out_size)
{
    const float* x       = (const float*)d_in[0];
    const float* noise   = (const float*)d_in[1];
    const float* W_agent = (const float*)d_in[2];
    const float* b_agent = (const float*)d_in[3];
    const float* W_ih    = (const float*)d_in[4];
    const float* W_hh    = (const float*)d_in[5];
    const float* b_ih    = (const float*)d_in[6];
    const float* b_hh    = (const float*)d_in[7];
    const float* W_out   = (const float*)d_in[8];
    const float* b_out   = (const float*)d_in[9];
    const float* W_emb   = (const float*)d_in[10];
    const float* b_emb   = (const float*)d_in[11];
    const float* sos     = (const float*)d_in[12];

    float* out = (float*)d_out;                     // sequence [B, L, V]
    float* ent = out + (size_t)Bdim * Ldim * Vdim;  // entropies [B, L]

    float *hbuf0, *ebuf, *lbuf, *gibuf, *ghbuf;
    cudaGetSymbolAddress((void**)&hbuf0, g_h);
    float* hbuf1 = hbuf0 + (size_t)Bdim * Hdim;
    cudaGetSymbolAddress((void**)&ebuf, g_e);
    cudaGetSymbolAddress((void**)&lbuf, g_logits);
    cudaGetSymbolAddress((void**)&gibuf, g_gi);
    cudaGetSymbolAddress((void**)&ghbuf, g_gh);

    const int SMEM = 49152;
    cudaFuncSetAttribute(gemm_tc, cudaFuncAttributeMaxDynamicSharedMemorySize, SMEM);

    // e0 = broadcast(sos)
    init_e0_kernel<<<(Bdim * Edim) / 256, 256>>>(sos);

    // h0 = x @ W_agent^T + b_agent
    gemm_tc<<<dim3(Hdim / 64, Bdim / 128), 128, SMEM>>>(
        x, DIN, W_agent, DIN, b_agent, hbuf0, Hdim);

    for (int l = 0; l < Ldim; l++) {
        float* hin  = (l & 1) ? hbuf1 : hbuf0;
        float* hout = (l & 1) ? hbuf0 : hbuf1;

        // Gi = e @ W_ih^T + b_ih   [B, 1536], K = 256
        gemm_tc<<<dim3(1536 / 64, Bdim / 128), 128, SMEM>>>(
            ebuf, Edim, W_ih, Edim, b_ih, gibuf, 3 * Hdim);
        // Gh = h @ W_hh^T + b_hh   [B, 1536], K = 512
        gemm_tc<<<dim3(1536 / 64, Bdim / 128), 128, SMEM>>>(
            hin, Hdim, W_hh, Hdim, b_hh, ghbuf, 3 * Hdim);
        // GRU update
        gru_ew<<<(Bdim * Hdim / 4) / 256, 256>>>(
            (const float4*)gibuf, (const float4*)ghbuf, (const float4*)hin,
            (float4*)hout);
        // logits = h_t @ W_out^T + b_out
        gemm_tc<<<dim3(Vdim / 64, Bdim / 128), 128, SMEM>>>(
            hout, Hdim, W_out, Hdim, b_out, lbuf, Vdim);
        // sample = softmax(logits + gumbel); entropy
        softmax_kernel<<<Bdim / 8, 256>>>(
            lbuf, noise + (size_t)l * Bdim * Vdim, out, ent, l);
        // e_{l+1} = sample @ W_emb^T + b_emb (reads sample from d_out)
        gemm_tc<<<dim3(Edim / 64, Bdim / 128), 128, SMEM>>>(
            out + (size_t)l * Vdim, Ldim * Vdim, W_emb, Vdim, b_emb, ebuf, Edim);
    }
    (void)in_sizes; (void)n_in; (void)out_size;
}

// round 4
// speedup vs baseline: 3.2569x; 1.8636x over previous
#include <cuda_runtime.h>
#include <cuda_bf16.h>
#include <math.h>
#include <stdint.h>

#define Bdim 4096
#define DIN  512
#define Hdim 512
#define Edim 256
#define Vdim 512
#define Ldim 32
#define MIN_REAL (-3.4028234663852886e38f)

// ---------------- scratch (device globals; no allocation allowed) ----------
__device__ float         g_h[2][(size_t)Bdim * Hdim];      // fp32 hidden (master)
__device__ __nv_bfloat16 g_abf[2][(size_t)Bdim * 768];     // [e | h] bf16, ping-pong
__device__ float         g_grz[(size_t)Bdim * 1024];       // summed r,z pre-activations
__device__ float         g_in[(size_t)Bdim * Hdim];        // i_n
__device__ float         g_hn[(size_t)Bdim * Hdim];        // h_n
__device__ float         g_logits[(size_t)Bdim * Vdim];
__device__ __nv_bfloat16 g_sbf[(size_t)Bdim * Vdim];       // bf16 sample
__device__ __nv_bfloat16 g_xbf[(size_t)Bdim * DIN];
__device__ __nv_bfloat16 g_wrz[1024 * 768];                // [Wih_rz | Whh_rz]
__device__ __nv_bfloat16 g_wihn[512 * 256];
__device__ __nv_bfloat16 g_whhn[512 * 512];
__device__ __nv_bfloat16 g_wo[512 * 512];
__device__ __nv_bfloat16 g_we[256 * 512];
__device__ __nv_bfloat16 g_wa[512 * 512];
__device__ float         g_brz[1024];

__device__ __forceinline__ float sigm(float x) { return 1.f / (1.f + expf(-x)); }

#define MMA_BF16(d, av, bv) \
    asm volatile("mma.sync.aligned.m16n8k16.row.col.f32.bf16.bf16.f32 " \
        "{%0,%1,%2,%3}, {%4,%5,%6,%7}, {%8,%9}, {%0,%1,%2,%3};" \
        : "+f"((d)[0]), "+f"((d)[1]), "+f"((d)[2]), "+f"((d)[3]) \
        : "r"((av).x), "r"((av).y), "r"((av).z), "r"((av).w), \
          "r"((bv).x), "r"((bv).y))

// ---------------- prep kernels ----------------------------------------------
__global__ void cvt_kernel(__nv_bfloat16* __restrict__ dst,
                           const float* __restrict__ src, int n) {
    int i = blockIdx.x * blockDim.x + threadIdx.x;
    if (i < n) dst[i] = __float2bfloat16_rn(src[i]);
}
__global__ void build_wrz_kernel(const float* __restrict__ Wih,
                                 const float* __restrict__ Whh) {
    int i = blockIdx.x * blockDim.x + threadIdx.x;   // 1024*768
    int g = i / 768, c = i % 768;
    float v = (c < 256) ? Wih[g * 256 + c] : Whh[g * 512 + (c - 256)];
    g_wrz[i] = __float2bfloat16_rn(v);
}
__global__ void build_brz_kernel(const float* __restrict__ bih,
                                 const float* __restrict__ bhh) {
    int i = blockIdx.x * blockDim.x + threadIdx.x;   // 1024
    g_brz[i] = bih[i] + bhh[i];
}
__global__ void init_e0_kernel(const float* __restrict__ sos) {
    int i = blockIdx.x * blockDim.x + threadIdx.x;   // B*256
    int b = i >> 8, c = i & 255;
    g_abf[0][(size_t)b * 768 + c] = __float2bfloat16_rn(sos[c]);
}

// ======================= bf16 tensor-core GEMM ==============================
// C[M,N] = A[M,K] @ W[N,K]^T + bias.  Block 128x128, 256 thr, K-block 32.
// 8 warps: wm=wid&3 (32 rows), wn=wid>>2 (64 cols). m16n8k16 fragments stored
// pre-permuted in SMEM -> conflict-free LDS.128 / LDS.64 in the hot loop.
__global__ __launch_bounds__(256) void gemm_bf(
    const __nv_bfloat16* __restrict__ A, int lda,
    const __nv_bfloat16* __restrict__ W, int K,
    const float* __restrict__ bias,
    float* __restrict__ C, int ldc,
    __nv_bfloat16* __restrict__ Cbf, int ldcb)
{
    __shared__ uint4 As[2][2][8][32];    // [stage][kstep][mtile][lane]
    __shared__ uint2 Bs[2][2][16][32];   // [stage][kstep][ntile][lane]
    const int tid = threadIdx.x, wid = tid >> 5, lane = tid & 31;
    const int wm = wid & 3, wn = wid >> 2;
    const int m0 = blockIdx.y << 7, n0 = blockIdx.x << 7;
    const int KB = K >> 5;

    float acc[2][8][4];
#pragma unroll
    for (int a = 0; a < 2; a++)
#pragma unroll
        for (int b = 0; b < 8; b++)
#pragma unroll
            for (int c = 0; c < 4; c++) acc[a][b][c] = 0.f;

    uint4 ra[2], rb[2];

    auto load_regs = [&](int kb) {
#pragma unroll
        for (int it = 0; it < 2; ++it) {
            int j = tid + (it << 8), r = j >> 2, ch = j & 3;
            ra[it] = *(const uint4*)(A + (size_t)(m0 + r) * lda + (kb << 5) + (ch << 3));
            rb[it] = *(const uint4*)(W + (size_t)(n0 + r) * K + (kb << 5) + (ch << 3));
        }
    };
    auto store_smem = [&](int s) {
#pragma unroll
        for (int it = 0; it < 2; ++it) {
            int j = tid + (it << 8), r = j >> 2, ch = j & 3;
            int ks = ch >> 1, h8 = ch & 1;
            {   // A fragment scatter
                int rr = r & 15, mt = r >> 4;
                int comp = (rr >> 3) + (h8 << 1);
                uint32_t* dst = (uint32_t*)&As[s][ks][mt][0];
                const uint32_t* w = (const uint32_t*)&ra[it];
                int L0 = (rr & 7) << 2;
#pragma unroll
                for (int pi = 0; pi < 4; ++pi)
                    dst[((L0 + pi) << 2) + comp] = w[pi];
            }
            {   // B fragment scatter
                int nt = r >> 3, nn = r & 7;
                uint32_t* dst = (uint32_t*)&Bs[s][ks][nt][0];
                const uint32_t* w = (const uint32_t*)&rb[it];
                int L0 = nn << 2;
#pragma unroll
                for (int pi = 0; pi < 4; ++pi)
                    dst[((L0 + pi) << 1) + h8] = w[pi];
            }
        }
    };
    auto compute = [&](int s) {
#pragma unroll
        for (int ks = 0; ks < 2; ++ks) {
            uint4 a0 = As[s][ks][(wm << 1) + 0][lane];
            uint4 a1 = As[s][ks][(wm << 1) + 1][lane];
            uint2 bf[8];
#pragma unroll
            for (int nt = 0; nt < 8; ++nt)
                bf[nt] = Bs[s][ks][(wn << 3) + nt][lane];
#pragma unroll
            for (int nt = 0; nt < 8; ++nt) {
                MMA_BF16(acc[0][nt], a0, bf[nt]);
                MMA_BF16(acc[1][nt], a1, bf[nt]);
            }
        }
    };

    load_regs(0);
    store_smem(0);
    __syncthreads();
    for (int kb = 0; kb < KB; ++kb) {
        if (kb + 1 < KB) load_regs(kb + 1);
        compute(kb & 1);
        if (kb + 1 < KB) {
            __syncthreads();
            store_smem((kb + 1) & 1);
            __syncthreads();
        }
    }

    // epilogue
#pragma unroll
    for (int mt = 0; mt < 2; ++mt) {
#pragma unroll
        for (int nt = 0; nt < 8; ++nt) {
            int row = m0 + (wm << 5) + (mt << 4) + (lane >> 2);
            int col = n0 + (wn << 6) + (nt << 3) + ((lane & 3) << 1);
            float2 bv = *(const float2*)&bias[col];
            float2 o0 = {acc[mt][nt][0] + bv.x, acc[mt][nt][1] + bv.y};
            float2 o1 = {acc[mt][nt][2] + bv.x, acc[mt][nt][3] + bv.y};
            if (C) {
                *(float2*)&C[(size_t)row * ldc + col] = o0;
                *(float2*)&C[(size_t)(row + 8) * ldc + col] = o1;
            }
            if (Cbf) {
                __nv_bfloat162 p0 = {__float2bfloat16_rn(o0.x), __float2bfloat16_rn(o0.y)};
                __nv_bfloat162 p1 = {__float2bfloat16_rn(o1.x), __float2bfloat16_rn(o1.y)};
                *(__nv_bfloat162*)&Cbf[(size_t)row * ldcb + col] = p0;
                *(__nv_bfloat162*)&Cbf[(size_t)(row + 8) * ldcb + col] = p1;
            }
        }
    }
}

// ======================= elementwise GRU update =============================
__global__ __launch_bounds__(256) void gru_ew(
    const float4* __restrict__ Grz, const float4* __restrict__ In,
    const float4* __restrict__ Hn, const float4* __restrict__ hin,
    float4* __restrict__ hout, __nv_bfloat16* __restrict__ habf)
{
    int i = blockIdx.x * blockDim.x + threadIdx.x;   // B * 128
    int b = i >> 7, jq = i & 127;
    float4 gr = Grz[(size_t)b * 256 + jq];
    float4 gz = Grz[(size_t)b * 256 + 128 + jq];
    float4 gi = In[(size_t)b * 128 + jq];
    float4 gh = Hn[(size_t)b * 128 + jq];
    float4 h = hin[(size_t)b * 128 + jq];
    float4 o;
    { float r = sigm(gr.x), z = sigm(gz.x);
      o.x = (1.f - z) * tanhf(gi.x + r * gh.x) + z * h.x; }
    { float r = sigm(gr.y), z = sigm(gz.y);
      o.y = (1.f - z) * tanhf(gi.y + r * gh.y) + z * h.y; }
    { float r = sigm(gr.z), z = sigm(gz.z);
      o.z = (1.f - z) * tanhf(gi.z + r * gh.z) + z * h.z; }
    { float r = sigm(gr.w), z = sigm(gz.w);
      o.w = (1.f - z) * tanhf(gi.w + r * gh.w) + z * h.w; }
    hout[(size_t)b * 128 + jq] = o;
    __nv_bfloat162 p0 = {__float2bfloat16_rn(o.x), __float2bfloat16_rn(o.y)};
    __nv_bfloat162 p1 = {__float2bfloat16_rn(o.z), __float2bfloat16_rn(o.w)};
    __nv_bfloat162* dst = (__nv_bfloat162*)(habf + (size_t)b * 768 + 256 + (jq << 2));
    dst[0] = p0; dst[1] = p1;
}

// ======================= gumbel softmax + entropy ===========================
__global__ __launch_bounds__(256) void softmax_kernel(
    const float* __restrict__ logits, const float* __restrict__ u,
    float* __restrict__ seq, float* __restrict__ ent,
    __nv_bfloat16* __restrict__ sbf, int l)
{
    const int warp = threadIdx.x >> 5, lane = threadIdx.x & 31;
    const int b = blockIdx.x * 8 + warp;
    const float* lrow = logits + (size_t)b * Vdim;
    const float* urow = u + (size_t)b * Vdim;

    float s[16];
    float m = -INFINITY;
#pragma unroll
    for (int i = 0; i < 16; i++) {
        float uu = urow[lane + 32 * i];
        float g = -logf(-logf(uu));
        s[i] = lrow[lane + 32 * i] + g;
        m = fmaxf(m, s[i]);
    }
#pragma unroll
    for (int o = 16; o; o >>= 1) m = fmaxf(m, __shfl_xor_sync(0xffffffffu, m, o));
    float sum = 0.f;
#pragma unroll
    for (int i = 0; i < 16; i++) { s[i] = expf(s[i] - m); sum += s[i]; }
#pragma unroll
    for (int o = 16; o; o >>= 1) sum += __shfl_xor_sync(0xffffffffu, sum, o);

    float inv = 1.f / sum;
    float eacc = 0.f;
    float* srow = seq + ((size_t)b * Ldim + l) * Vdim;
    __nv_bfloat16* brow = sbf + (size_t)b * Vdim;
#pragma unroll
    for (int i = 0; i < 16; i++) {
        float p = s[i] * inv;
        srow[lane + 32 * i] = p;
        brow[lane + 32 * i] = __float2bfloat16_rn(p);
        float t = fmaxf(log2f(p), MIN_REAL);
        eacc -= p * t;
    }
#pragma unroll
    for (int o = 16; o; o >>= 1) eacc += __shfl_xor_sync(0xffffffffu, eacc, o);
    if (lane == 0) ent[(size_t)b * Ldim + l] = eacc;
}

// ======================= host launcher ======================================
extern "C" void kernel_launch(void* const* d_in, const int* in_sizes, int n_in,
                              void* d_out, int out_size)
{
    const float* x       = (const float*)d_in[0];
    const float* noise   = (const float*)d_in[1];
    const float* W_agent = (const float*)d_in[2];
    const float* b_agent = (const float*)d_in[3];
    const float* W_ih    = (const float*)d_in[4];
    const float* W_hh    = (const float*)d_in[5];
    const float* b_ih    = (const float*)d_in[6];
    const float* b_hh    = (const float*)d_in[7];
    const float* W_out   = (const float*)d_in[8];
    const float* b_out   = (const float*)d_in[9];
    const float* W_emb   = (const float*)d_in[10];
    const float* b_emb   = (const float*)d_in[11];
    const float* sos     = (const float*)d_in[12];

    float* out = (float*)d_out;
    float* ent = out + (size_t)Bdim * Ldim * Vdim;

    float *hbuf0, *grz, *inb, *hnb, *lbuf, *brz;
    __nv_bfloat16 *abf0, *sbf, *xbf, *wrz, *wihn, *whhn, *wo, *we, *wa;
    cudaGetSymbolAddress((void**)&hbuf0, g_h);
    float* hbuf1 = hbuf0 + (size_t)Bdim * Hdim;
    cudaGetSymbolAddress((void**)&abf0, g_abf);
    __nv_bfloat16* abf1 = abf0 + (size_t)Bdim * 768;
    cudaGetSymbolAddress((void**)&grz, g_grz);
    cudaGetSymbolAddress((void**)&inb, g_in);
    cudaGetSymbolAddress((void**)&hnb, g_hn);
    cudaGetSymbolAddress((void**)&lbuf, g_logits);
    cudaGetSymbolAddress((void**)&sbf, g_sbf);
    cudaGetSymbolAddress((void**)&xbf, g_xbf);
    cudaGetSymbolAddress((void**)&wrz, g_wrz);
    cudaGetSymbolAddress((void**)&wihn, g_wihn);
    cudaGetSymbolAddress((void**)&whhn, g_whhn);
    cudaGetSymbolAddress((void**)&wo, g_wo);
    cudaGetSymbolAddress((void**)&we, g_we);
    cudaGetSymbolAddress((void**)&wa, g_wa);
    cudaGetSymbolAddress((void**)&brz, g_brz);

    // ---- one-time prep ----
    build_wrz_kernel<<<(1024 * 768) / 256, 256>>>(W_ih, W_hh);
    build_brz_kernel<<<4, 256>>>(b_ih, b_hh);
    cvt_kernel<<<(512 * 256) / 256, 256>>>(wihn, W_ih + 1024 * 256, 512 * 256);
    cvt_kernel<<<(512 * 512) / 256, 256>>>(whhn, W_hh + 1024 * 512, 512 * 512);
    cvt_kernel<<<(512 * 512) / 256, 256>>>(wo, W_out, 512 * 512);
    cvt_kernel<<<(256 * 512) / 256, 256>>>(we, W_emb, 256 * 512);
    cvt_kernel<<<(512 * 512) / 256, 256>>>(wa, W_agent, 512 * 512);
    cvt_kernel<<<(Bdim * DIN) / 256, 256>>>(xbf, x, Bdim * DIN);
    init_e0_kernel<<<(Bdim * Edim) / 256, 256>>>(sos);

    // h0 = x @ W_agent^T + b_agent  (fp32 master + bf16 into A'[0] h-slot)
    gemm_bf<<<dim3(4, 32), 256>>>(xbf, DIN, wa, DIN, b_agent,
                                  hbuf0, Hdim, abf0 + 256, 768);

    for (int l = 0; l < Ldim; l++) {
        __nv_bfloat16* Ain  = (l & 1) ? abf1 : abf0;
        __nv_bfloat16* Anxt = (l & 1) ? abf0 : abf1;
        float* hin  = (l & 1) ? hbuf1 : hbuf0;
        float* hout = (l & 1) ? hbuf0 : hbuf1;

        // r,z (summed) : [e|h] @ Wrz^T + (b_ih+b_hh)   K=768
        gemm_bf<<<dim3(8, 32), 256>>>(Ain, 768, wrz, 768, brz,
                                      grz, 1024, (__nv_bfloat16*)0, 0);
        // i_n = e @ Wih_n^T + b_ih_n                    K=256
        gemm_bf<<<dim3(4, 32), 256>>>(Ain, 768, wihn, 256, b_ih + 1024,
                                      inb, 512, (__nv_bfloat16*)0, 0);
        // h_n = h @ Whh_n^T + b_hh_n                    K=512
        gemm_bf<<<dim3(4, 32), 256>>>(Ain + 256, 768, whhn, 512, b_hh + 1024,
                                      hnb, 512, (__nv_bfloat16*)0, 0);
        // GRU update -> fp32 h + bf16 h into A'[next]
        gru_ew<<<(Bdim * 128) / 256, 256>>>(
            (const float4*)grz, (const float4*)inb, (const float4*)hnb,
            (const float4*)hin, (float4*)hout, Anxt);
        // logits = h_t @ W_out^T + b_out                K=512
        gemm_bf<<<dim3(4, 32), 256>>>(Anxt + 256, 768, wo, 512, b_out,
                                      lbuf, 512, (__nv_bfloat16*)0, 0);
        // sample + entropy (+ bf16 sample)
        softmax_kernel<<<Bdim / 8, 256>>>(
            lbuf, noise + (size_t)l * Bdim * Vdim, out, ent, sbf, l);
        // e_{l+1} = sample @ W_emb^T + b_emb -> bf16 into A'[next] e-slot
        gemm_bf<<<dim3(2, 32), 256>>>(sbf, 512, we, 512, b_emb,
                                      (float*)0, 0, Anxt, 768);
    }
    (void)in_sizes; (void)n_in; (void)out_size;
}

// round 5
// speedup vs baseline: 5.1127x; 1.5698x over previous
#include <cuda_runtime.h>
#include <cuda_bf16.h>
#include <math.h>
#include <stdint.h>

#define Bdim 4096
#define DIN  512
#define Hdim 512
#define Edim 256
#define Vdim 512
#define Ldim 32
#define MIN_REAL (-3.4028234663852886e38f)

// ---------------- scratch (device globals; no allocation allowed) ----------
__device__ float         g_h[2][(size_t)Bdim * Hdim];      // fp32 hidden (master)
__device__ __nv_bfloat16 g_abf[2][(size_t)Bdim * 768];     // [e | h] bf16, ping-pong
__device__ float         g_grz[(size_t)Bdim * 1024];       // summed r,z pre-activations
__device__ float         g_in[(size_t)Bdim * Hdim];        // i_n
__device__ float         g_hn[(size_t)Bdim * Hdim];        // h_n
__device__ float         g_logits[(size_t)Bdim * Vdim];
__device__ __nv_bfloat16 g_sbf[(size_t)Bdim * Vdim];       // bf16 sample
__device__ __nv_bfloat16 g_xbf[(size_t)Bdim * DIN];
__device__ __nv_bfloat16 g_wrz[1024 * 768];                // [Wih_rz | Whh_rz]
__device__ __nv_bfloat16 g_wihn[512 * 256];
__device__ __nv_bfloat16 g_whhn[512 * 512];
__device__ __nv_bfloat16 g_wo[512 * 512];
__device__ __nv_bfloat16 g_we[256 * 512];
__device__ __nv_bfloat16 g_wa[512 * 512];
__device__ float         g_brz[1024];

__device__ __forceinline__ float sigm(float x) { return 1.f / (1.f + expf(-x)); }

#define MMA_BF16(d, a, b) \
    asm volatile("mma.sync.aligned.m16n8k16.row.col.f32.bf16.bf16.f32 " \
        "{%0,%1,%2,%3}, {%4,%5,%6,%7}, {%8,%9}, {%0,%1,%2,%3};" \
        : "+f"((d)[0]), "+f"((d)[1]), "+f"((d)[2]), "+f"((d)[3]) \
        : "r"((a)[0]), "r"((a)[1]), "r"((a)[2]), "r"((a)[3]), \
          "r"((b)[0]), "r"((b)[1]))

#define LDM_X4(d, addr) \
    asm volatile("ldmatrix.sync.aligned.m8n8.x4.shared.b16 {%0,%1,%2,%3}, [%4];" \
        : "=r"((d)[0]), "=r"((d)[1]), "=r"((d)[2]), "=r"((d)[3]) : "r"(addr))

__device__ __forceinline__ void cp16(uint32_t dst, const void* src) {
    asm volatile("cp.async.cg.shared.global [%0], [%1], 16;" :: "r"(dst), "l"(src) : "memory");
}
#define CP_COMMIT  asm volatile("cp.async.commit_group;" ::: "memory")
#define CP_WAIT2   asm volatile("cp.async.wait_group 2;" ::: "memory")

// ---------------- prep kernels ----------------------------------------------
__global__ void cvt_kernel(__nv_bfloat16* __restrict__ dst,
                           const float* __restrict__ src, int n) {
    int i = blockIdx.x * blockDim.x + threadIdx.x;
    if (i < n) dst[i] = __float2bfloat16_rn(src[i]);
}
__global__ void build_wrz_kernel(const float* __restrict__ Wih,
                                 const float* __restrict__ Whh) {
    int i = blockIdx.x * blockDim.x + threadIdx.x;   // 1024*768
    int g = i / 768, c = i % 768;
    float v = (c < 256) ? Wih[g * 256 + c] : Whh[g * 512 + (c - 256)];
    g_wrz[i] = __float2bfloat16_rn(v);
}
__global__ void build_brz_kernel(const float* __restrict__ bih,
                                 const float* __restrict__ bhh) {
    int i = blockIdx.x * blockDim.x + threadIdx.x;   // 1024
    g_brz[i] = bih[i] + bhh[i];
}
__global__ void init_e0_kernel(const float* __restrict__ sos) {
    int i = blockIdx.x * blockDim.x + threadIdx.x;   // B*256
    int b = i >> 8, c = i & 255;
    g_abf[0][(size_t)b * 768 + c] = __float2bfloat16_rn(sos[c]);
}

// ======================= bf16 tensor-core GEMM ==============================
// C[M,N] = A[M,K] @ W[N,K]^T + bias.  Block 128x128, 256 thr, K-block 32.
// 4-stage cp.async pipeline into XOR-swizzled SMEM; ldmatrix.x4 fragment loads.
// 8 warps: wm=wid&3 (32 rows), wn=wid>>2 (64 cols); m16n8k16, fp32 accum.
__global__ __launch_bounds__(256, 2) void gemm_bf(
    const __nv_bfloat16* __restrict__ A, int lda,
    const __nv_bfloat16* __restrict__ W, int K,
    const float* __restrict__ bias,
    float* __restrict__ C, int ldc,
    __nv_bfloat16* __restrict__ Cbf, int ldcb)
{
    __shared__ __align__(1024) char smem[4 * 16384];   // stage: A 8K | B 8K
    const int tid = threadIdx.x, wid = tid >> 5, lane = tid & 31;
    const int wm = wid & 3, wn = wid >> 2;
    const int m0 = blockIdx.y << 7, n0 = blockIdx.x << 7;
    const int KB = K >> 5;
    const uint32_t smbase = (uint32_t)__cvta_generic_to_shared(smem);

    float acc[2][8][4];
#pragma unroll
    for (int a = 0; a < 2; a++)
#pragma unroll
        for (int b = 0; b < 8; b++)
#pragma unroll
            for (int c = 0; c < 4; c++) acc[a][b][c] = 0.f;

    const int cr = tid >> 2, cc = tid & 3;          // cp.async chunk geometry
    auto issue = [&](int kb, int s) {
        uint32_t sb = smbase + ((uint32_t)s << 14);
#pragma unroll
        for (int it = 0; it < 2; ++it) {
            int rr = cr + (it << 6);
            uint32_t off = (uint32_t)(((rr << 2) + (cc ^ ((rr >> 1) & 3))) << 4);
            cp16(sb + off,         A + (size_t)(m0 + rr) * lda + (kb << 5) + (cc << 3));
            cp16(sb + 8192 + off,  W + (size_t)(n0 + rr) * K   + (kb << 5) + (cc << 3));
        }
    };

    // ldmatrix lane geometry (constant per thread)
    const int arow0 = (wm << 5) + (lane & 7) + (((lane >> 3) & 1) << 3);
    const int acb   = (lane >> 4) & 1;
    const int nrow0 = (wn << 6) + (lane & 7) + (((lane >> 4) & 1) << 3);
    const int bcb   = (lane >> 3) & 1;

    auto compute = [&](int s) {
        uint32_t ab = smbase + ((uint32_t)s << 14);
        uint32_t bb = ab + 8192;
#pragma unroll
        for (int ks = 0; ks < 2; ++ks) {
            uint32_t a[2][4];
#pragma unroll
            for (int mt = 0; mt < 2; ++mt) {
                int row = arow0 + (mt << 4);
                int ch = (ks << 1) + acb;
                uint32_t addr = ab + (uint32_t)(((row << 2) + (ch ^ ((row >> 1) & 3))) << 4);
                LDM_X4(a[mt], addr);
            }
            uint32_t b[8][2];
#pragma unroll
            for (int p = 0; p < 4; ++p) {
                int row = nrow0 + (p << 4);
                int ch = (ks << 1) + bcb;
                uint32_t addr = bb + (uint32_t)(((row << 2) + (ch ^ ((row >> 1) & 3))) << 4);
                uint32_t t[4];
                LDM_X4(t, addr);
                b[2 * p][0] = t[0]; b[2 * p][1] = t[1];
                b[2 * p + 1][0] = t[2]; b[2 * p + 1][1] = t[3];
            }
#pragma unroll
            for (int nt = 0; nt < 8; ++nt) {
                MMA_BF16(acc[0][nt], a[0], b[nt]);
                MMA_BF16(acc[1][nt], a[1], b[nt]);
            }
        }
    };

    issue(0, 0); CP_COMMIT;
    issue(1, 1); CP_COMMIT;
    issue(2, 2); CP_COMMIT;
#pragma unroll 1
    for (int kb = 0; kb < KB; ++kb) {
        CP_WAIT2;
        __syncthreads();
        if (kb + 3 < KB) issue(kb + 3, (kb + 3) & 3);
        CP_COMMIT;
        compute(kb & 3);
    }

    // epilogue
#pragma unroll
    for (int mt = 0; mt < 2; ++mt) {
#pragma unroll
        for (int nt = 0; nt < 8; ++nt) {
            int row = m0 + (wm << 5) + (mt << 4) + (lane >> 2);
            int col = n0 + (wn << 6) + (nt << 3) + ((lane & 3) << 1);
            float2 bv = *(const float2*)&bias[col];
            float2 o0 = {acc[mt][nt][0] + bv.x, acc[mt][nt][1] + bv.y};
            float2 o1 = {acc[mt][nt][2] + bv.x, acc[mt][nt][3] + bv.y};
            if (C) {
                *(float2*)&C[(size_t)row * ldc + col] = o0;
                *(float2*)&C[(size_t)(row + 8) * ldc + col] = o1;
            }
            if (Cbf) {
                __nv_bfloat162 p0 = {__float2bfloat16_rn(o0.x), __float2bfloat16_rn(o0.y)};
                __nv_bfloat162 p1 = {__float2bfloat16_rn(o1.x), __float2bfloat16_rn(o1.y)};
                *(__nv_bfloat162*)&Cbf[(size_t)row * ldcb + col] = p0;
                *(__nv_bfloat162*)&Cbf[(size_t)(row + 8) * ldcb + col] = p1;
            }
        }
    }
}

// ======================= elementwise GRU update =============================
__global__ __launch_bounds__(256) void gru_ew(
    const float4* __restrict__ Grz, const float4* __restrict__ In,
    const float4* __restrict__ Hn, const float4* __restrict__ hin,
    float4* __restrict__ hout, __nv_bfloat16* __restrict__ habf)
{
    int i = blockIdx.x * blockDim.x + threadIdx.x;   // B * 128
    int b = i >> 7, jq = i & 127;
    float4 gr = Grz[(size_t)b * 256 + jq];
    float4 gz = Grz[(size_t)b * 256 + 128 + jq];
    float4 gi = In[(size_t)b * 128 + jq];
    float4 gh = Hn[(size_t)b * 128 + jq];
    float4 h = hin[(size_t)b * 128 + jq];
    float4 o;
    { float r = sigm(gr.x), z = sigm(gz.x);
      o.x = (1.f - z) * tanhf(gi.x + r * gh.x) + z * h.x; }
    { float r = sigm(gr.y), z = sigm(gz.y);
      o.y = (1.f - z) * tanhf(gi.y + r * gh.y) + z * h.y; }
    { float r = sigm(gr.z), z = sigm(gz.z);
      o.z = (1.f - z) * tanhf(gi.z + r * gh.z) + z * h.z; }
    { float r = sigm(gr.w), z = sigm(gz.w);
      o.w = (1.f - z) * tanhf(gi.w + r * gh.w) + z * h.w; }
    hout[(size_t)b * 128 + jq] = o;
    __nv_bfloat162 p0 = {__float2bfloat16_rn(o.x), __float2bfloat16_rn(o.y)};
    __nv_bfloat162 p1 = {__float2bfloat16_rn(o.z), __float2bfloat16_rn(o.w)};
    __nv_bfloat162* dst = (__nv_bfloat162*)(habf + (size_t)b * 768 + 256 + (jq << 2));
    dst[0] = p0; dst[1] = p1;
}

// ======================= gumbel softmax + entropy ===========================
__global__ __launch_bounds__(256) void softmax_kernel(
    const float* __restrict__ logits, const float* __restrict__ u,
    float* __restrict__ seq, float* __restrict__ ent,
    __nv_bfloat16* __restrict__ sbf, int l)
{
    const int warp = threadIdx.x >> 5, lane = threadIdx.x & 31;
    const int b = blockIdx.x * 8 + warp;
    const float* lrow = logits + (size_t)b * Vdim;
    const float* urow = u + (size_t)b * Vdim;

    float s[16];
    float m = -INFINITY;
#pragma unroll
    for (int i = 0; i < 16; i++) {
        float uu = urow[lane + 32 * i];
        float g = -logf(-logf(uu));
        s[i] = lrow[lane + 32 * i] + g;
        m = fmaxf(m, s[i]);
    }
#pragma unroll
    for (int o = 16; o; o >>= 1) m = fmaxf(m, __shfl_xor_sync(0xffffffffu, m, o));
    float sum = 0.f;
#pragma unroll
    for (int i = 0; i < 16; i++) { s[i] = expf(s[i] - m); sum += s[i]; }
#pragma unroll
    for (int o = 16; o; o >>= 1) sum += __shfl_xor_sync(0xffffffffu, sum, o);

    float inv = 1.f / sum;
    float eacc = 0.f;
    float* srow = seq + ((size_t)b * Ldim + l) * Vdim;
    __nv_bfloat16* brow = sbf + (size_t)b * Vdim;
#pragma unroll
    for (int i = 0; i < 16; i++) {
        float p = s[i] * inv;
        srow[lane + 32 * i] = p;
        brow[lane + 32 * i] = __float2bfloat16_rn(p);
        float t = fmaxf(log2f(p), MIN_REAL);
        eacc -= p * t;
    }
#pragma unroll
    for (int o = 16; o; o >>= 1) eacc += __shfl_xor_sync(0xffffffffu, eacc, o);
    if (lane == 0) ent[(size_t)b * Ldim + l] = eacc;
}

// ======================= host launcher ======================================
extern "C" void kernel_launch(void* const* d_in, const int* in_sizes, int n_in,
                              void* d_out, int out_size)
{
    const float* x       = (const float*)d_in[0];
    const float* noise   = (const float*)d_in[1];
    const float* W_agent = (const float*)d_in[2];
    const float* b_agent = (const float*)d_in[3];
    const float* W_ih    = (const float*)d_in[4];
    const float* W_hh    = (const float*)d_in[5];
    const float* b_ih    = (const float*)d_in[6];
    const float* b_hh    = (const float*)d_in[7];
    const float* W_out   = (const float*)d_in[8];
    const float* b_out   = (const float*)d_in[9];
    const float* W_emb   = (const float*)d_in[10];
    const float* b_emb   = (const float*)d_in[11];
    const float* sos     = (const float*)d_in[12];

    float* out = (float*)d_out;
    float* ent = out + (size_t)Bdim * Ldim * Vdim;

    float *hbuf0, *grz, *inb, *hnb, *lbuf, *brz;
    __nv_bfloat16 *abf0, *sbf, *xbf, *wrz, *wihn, *whhn, *wo, *we, *wa;
    cudaGetSymbolAddress((void**)&hbuf0, g_h);
    float* hbuf1 = hbuf0 + (size_t)Bdim * Hdim;
    cudaGetSymbolAddress((void**)&abf0, g_abf);
    __nv_bfloat16* abf1 = abf0 + (size_t)Bdim * 768;
    cudaGetSymbolAddress((void**)&grz, g_grz);
    cudaGetSymbolAddress((void**)&inb, g_in);
    cudaGetSymbolAddress((void**)&hnb, g_hn);
    cudaGetSymbolAddress((void**)&lbuf, g_logits);
    cudaGetSymbolAddress((void**)&sbf, g_sbf);
    cudaGetSymbolAddress((void**)&xbf, g_xbf);
    cudaGetSymbolAddress((void**)&wrz, g_wrz);
    cudaGetSymbolAddress((void**)&wihn, g_wihn);
    cudaGetSymbolAddress((void**)&whhn, g_whhn);
    cudaGetSymbolAddress((void**)&wo, g_wo);
    cudaGetSymbolAddress((void**)&we, g_we);
    cudaGetSymbolAddress((void**)&wa, g_wa);
    cudaGetSymbolAddress((void**)&brz, g_brz);

    // ---- one-time prep ----
    build_wrz_kernel<<<(1024 * 768) / 256, 256>>>(W_ih, W_hh);
    build_brz_kernel<<<4, 256>>>(b_ih, b_hh);
    cvt_kernel<<<(512 * 256) / 256, 256>>>(wihn, W_ih + 1024 * 256, 512 * 256);
    cvt_kernel<<<(512 * 512) / 256, 256>>>(whhn, W_hh + 1024 * 512, 512 * 512);
    cvt_kernel<<<(512 * 512) / 256, 256>>>(wo, W_out, 512 * 512);
    cvt_kernel<<<(256 * 512) / 256, 256>>>(we, W_emb, 256 * 512);
    cvt_kernel<<<(512 * 512) / 256, 256>>>(wa, W_agent, 512 * 512);
    cvt_kernel<<<(Bdim * DIN) / 256, 256>>>(xbf, x, Bdim * DIN);
    init_e0_kernel<<<(Bdim * Edim) / 256, 256>>>(sos);

    // h0 = x @ W_agent^T + b_agent  (fp32 master + bf16 into A'[0] h-slot)
    gemm_bf<<<dim3(4, 32), 256>>>(xbf, DIN, wa, DIN, b_agent,
                                  hbuf0, Hdim, abf0 + 256, 768);

    for (int l = 0; l < Ldim; l++) {
        __nv_bfloat16* Ain  = (l & 1) ? abf1 : abf0;
        __nv_bfloat16* Anxt = (l & 1) ? abf0 : abf1;
        float* hin  = (l & 1) ? hbuf1 : hbuf0;
        float* hout = (l & 1) ? hbuf0 : hbuf1;

        // r,z (summed) : [e|h] @ Wrz^T + (b_ih+b_hh)   K=768
        gemm_bf<<<dim3(8, 32), 256>>>(Ain, 768, wrz, 768, brz,
                                      grz, 1024, (__nv_bfloat16*)0, 0);
        // i_n = e @ Wih_n^T + b_ih_n                    K=256
        gemm_bf<<<dim3(4, 32), 256>>>(Ain, 768, wihn, 256, b_ih + 1024,
                                      inb, 512, (__nv_bfloat16*)0, 0);
        // h_n = h @ Whh_n^T + b_hh_n                    K=512
        gemm_bf<<<dim3(4, 32), 256>>>(Ain + 256, 768, whhn, 512, b_hh + 1024,
                                      hnb, 512, (__nv_bfloat16*)0, 0);
        // GRU update -> fp32 h + bf16 h into A'[next]
        gru_ew<<<(Bdim * 128) / 256, 256>>>(
            (const float4*)grz, (const float4*)inb, (const float4*)hnb,
            (const float4*)hin, (float4*)hout, Anxt);
        // logits = h_t @ W_out^T + b_out                K=512
        gemm_bf<<<dim3(4, 32), 256>>>(Anxt + 256, 768, wo, 512, b_out,
                                      lbuf, 512, (__nv_bfloat16*)0, 0);
        // sample + entropy (+ bf16 sample)
        softmax_kernel<<<Bdim / 8, 256>>>(
            lbuf, noise + (size_t)l * Bdim * Vdim, out, ent, sbf, l);
        // e_{l+1} = sample @ W_emb^T + b_emb -> bf16 into A'[next] e-slot
        gemm_bf<<<dim3(2, 32), 256>>>(sbf, 512, we, 512, b_emb,
                                      (float*)0, 0, Anxt, 768);
    }
    (void)in_sizes; (void)n_in; (void)out_size;
}